// round 16
// baseline (speedup 1.0000x reference)
#include <cuda_runtime.h>
#include <cuda_fp16.h>
#include <math.h>
#include <stdint.h>

#define N_TOK 4096
#define C_DIM 256
#define BATCH 2
#define HEADS 8
#define HDIM 32

// exp2 scale folded into Q at GEMM epilogue: (1/sqrt(32)) * log2(e)
#define KL2_SCALE (0.17677669529663687f * 1.4426950408889634f)

// ===========================================================================
// Helpers
// ===========================================================================
__device__ __forceinline__ uint32_t smem_to_u32(const void* smem_ptr) {
    uint32_t addr;
    asm("{ .reg .u64 tmp; cvta.to.shared.u64 tmp, %1; cvt.u32.u64 %0, tmp; }"
        : "=r"(addr) : "l"(smem_ptr));
    return addr;
}

#define STS128(r0, r1, r2, r3, smem_addr) \
    asm volatile("st.shared.v4.b32 [%0], {%1, %2, %3, %4};" \
        :: "r"(smem_addr), "r"(r0), "r"(r1), "r"(r2), "r"(r3) : "memory")

__device__ __forceinline__ void cp_async16(uint32_t smem, const void* gptr) {
    asm volatile("cp.async.cg.shared.global [%0], [%1], 16;"
        :: "r"(smem), "l"(gptr) : "memory");
}
#define CP_COMMIT() asm volatile("cp.async.commit_group;" ::: "memory")
#define CP_WAIT0()  asm volatile("cp.async.wait_group 0;" ::: "memory")

__device__ __forceinline__ void ldsm_x4(uint32_t addr, uint32_t* r) {
    asm volatile("ldmatrix.sync.aligned.m8n8.x4.shared.b16 {%0,%1,%2,%3}, [%4];"
        : "=r"(r[0]), "=r"(r[1]), "=r"(r[2]), "=r"(r[3]) : "r"(addr));
}

__device__ __forceinline__ void mma16816(float* d, const uint32_t* a,
                                         uint32_t b0, uint32_t b1) {
    asm volatile(
        "mma.sync.aligned.m16n8k16.row.col.f32.f16.f16.f32 "
        "{%0,%1,%2,%3}, {%4,%5,%6,%7}, {%8,%9}, {%0,%1,%2,%3};"
        : "+f"(d[0]), "+f"(d[1]), "+f"(d[2]), "+f"(d[3])
        : "r"(a[0]), "r"(a[1]), "r"(a[2]), "r"(a[3]), "r"(b0), "r"(b1));
}

__device__ __forceinline__ uint32_t ex2_f16x2(uint32_t x) {
    uint32_t y;
    asm("ex2.approx.f16x2 %0, %1;" : "=r"(y) : "r"(x));
    return y;
}

// ===========================================================================
// Global scratch (no allocations allowed)
// ===========================================================================
__device__ __half g_xT[(size_t)BATCH * N_TOK * C_DIM];     // [b][n][c] hi only
__device__ __half g_whi[(size_t)3 * C_DIM * C_DIM];        // [o][c]
__device__ __half g_wlo[(size_t)3 * C_DIM * C_DIM];
__device__ __half g_Qhi[(size_t)16 * N_TOK * HDIM];        // [bh][tok][ch], pre-scaled by KL2
__device__ __half g_Khi[(size_t)16 * N_TOK * HDIM];        // [bh][tok][ch]
__device__ __half g_Vhi[(size_t)16 * HDIM * N_TOK];        // [bh][ch][tok]

// ===========================================================================
// Kernel A: transpose x: [b][c][n] fp32 -> [b][n][c] fp16 (hi only)
// ===========================================================================
__global__ __launch_bounds__(256) void convert_x_kernel(const float* __restrict__ x)
{
    __shared__ float t[32][33];
    const int n0 = blockIdx.x * 32;
    const int c0 = blockIdx.y * 32;
    const int b  = blockIdx.z;

    const float* src = x + ((size_t)b * C_DIM + c0) * N_TOK;
    for (int cy = threadIdx.y; cy < 32; cy += 8)
        t[cy][threadIdx.x] = src[(size_t)cy * N_TOK + n0 + threadIdx.x];
    __syncthreads();

    __half* hi = g_xT + ((size_t)b * N_TOK + n0) * C_DIM + c0;
    for (int ny = threadIdx.y; ny < 32; ny += 8)
        hi[(size_t)ny * C_DIM + threadIdx.x] =
            __float2half_rn(t[threadIdx.x][ny]);
}

// ===========================================================================
// Kernel B: split w: [o][c] fp32 -> hi/lo fp16 (same layout)
// ===========================================================================
__global__ __launch_bounds__(256) void convert_w_kernel(const float* __restrict__ w)
{
    int idx = blockIdx.x * 256 + threadIdx.x;
    if (idx < 3 * C_DIM * C_DIM) {
        float v = w[idx];
        __half h1 = __float2half_rn(v);
        g_whi[idx] = h1;
        g_wlo[idx] = __float2half_rn(v - __half2float(h1));
    }
}

// ===========================================================================
// Merged QKV GEMM kernel. grid (64, 12, 2), block 128.
//   blockIdx.y 0..7  : QK branch — out[n][o], A = xT rows, B = w hi/lo rows
//                      Q outputs (o<256) are pre-scaled by KL2_SCALE.
//   blockIdx.y 8..11 : V branch  — out[o][n], A = w hi/lo rows, B = xT rows
// ===========================================================================
__global__ __launch_bounds__(128) void qkv_gemm_kernel(const float* __restrict__ bias)
{
    __shared__ __align__(16) uint8_t smem[3 * 8192];

    const int tid  = threadIdx.x;
    const int lane = tid & 31;
    const int warp = tid >> 5;
    const int n0   = blockIdx.x * 64;
    const int b    = blockIdx.z;
    const int m0   = warp * 16;

    const int trow = (lane & 7) + ((lane >> 4) << 3);
    const int csel = (lane >> 3) & 1;
    const int aRow = m0 + (lane & 15);
    const int aCs  = lane >> 4;

    float acc[8][4];
#pragma unroll
    for (int i = 0; i < 8; i++)
#pragma unroll
        for (int j = 0; j < 4; j++) acc[i][j] = 0.f;

    const __half* xb = g_xT + (size_t)b * N_TOK * C_DIM;

    if (blockIdx.y < 8) {
        // ---------------- QK branch ----------------
        const int o0 = blockIdx.y * 64;   // 0..448
        const uint32_t sXa = smem_to_u32(smem);           // 8 KB x tile
        const uint32_t sWa = smem_to_u32(smem + 8192);    // 16 KB w hi/lo

        for (int kc = 0; kc < 4; kc++) {
            const int kc0 = kc * 64;
            for (int i = tid; i < 512; i += 128) {
                int row = i >> 3, cc = i & 7;
                uint32_t off = (uint32_t)(row * 128 + ((cc ^ (row & 7)) << 4));
                cp_async16(sXa + off,
                           (const void*)(xb + (size_t)(n0 + row) * C_DIM + kc0 + cc * 8));
            }
            for (int i = tid; i < 1024; i += 128) {
                int arr = i >> 9, rem = i & 511, row = rem >> 3, cc = rem & 7;
                uint32_t off = (uint32_t)(arr * 8192 + row * 128 +
                                          ((cc ^ (row & 7)) << 4));
                const __half* sp = (arr ? g_wlo : g_whi) +
                    (size_t)(o0 + row) * C_DIM + kc0 + cc * 8;
                cp_async16(sWa + off, (const void*)sp);
            }
            CP_COMMIT();
            CP_WAIT0();
            __syncthreads();

#pragma unroll
            for (int ks = 0; ks < 4; ks++) {
                uint32_t ahi[4];
                ldsm_x4(sXa + (uint32_t)(aRow * 128 +
                        (((ks * 2 + aCs) ^ (aRow & 7)) << 4)), ahi);
#pragma unroll
                for (int g = 0; g < 4; g++) {
                    uint32_t bhi[4], blo[4];
                    int row = g * 16 + trow;
                    uint32_t off = (uint32_t)(row * 128 +
                        (((ks * 2 + csel) ^ (row & 7)) << 4));
                    ldsm_x4(sWa + off, bhi);
                    ldsm_x4(sWa + 8192 + off, blo);
#pragma unroll
                    for (int hf = 0; hf < 2; hf++) {
                        float* d = acc[g * 2 + hf];
                        const int o = hf * 2;
                        mma16816(d, ahi, bhi[o], bhi[o + 1]);
                        mma16816(d, ahi, blo[o], blo[o + 1]);
                    }
                }
            }
            __syncthreads();
        }

        const int r  = lane >> 2;
        const int c0 = 2 * (lane & 3);
        const int n  = n0 + m0 + r;
        const bool isK = (o0 >= 256);
        __half* dst = isK ? g_Khi : g_Qhi;
        const float sc = isK ? 1.f : KL2_SCALE;   // fold exp2 scale into Q
#pragma unroll
        for (int nt = 0; nt < 8; nt++) {
            int og = o0 + nt * 8 + c0;
            int ol = og & 255;
            int bh = b * 8 + (ol >> 5);
            int ch = ol & 31;
            float b0 = bias[og], b1 = bias[og + 1];
            __half2 h0 = __floats2half2_rn((acc[nt][0] + b0) * sc,
                                           (acc[nt][1] + b1) * sc);
            __half2 h1 = __floats2half2_rn((acc[nt][2] + b0) * sc,
                                           (acc[nt][3] + b1) * sc);
            size_t base = ((size_t)bh * N_TOK + n) * HDIM + ch;
            *(__half2*)(dst + base) = h0;
            *(__half2*)(dst + base + 8 * HDIM) = h1;
        }
    } else {
        // ---------------- V branch ----------------
        const int o0 = (blockIdx.y - 8) * 64;   // 0..192 (V-local)
        const uint32_t sWa = smem_to_u32(smem);           // 16 KB w hi/lo
        const uint32_t sXa = smem_to_u32(smem + 16384);   // 8 KB x tile

        for (int kc = 0; kc < 4; kc++) {
            const int kc0 = kc * 64;
            for (int i = tid; i < 1024; i += 128) {
                int arr = i >> 9, rem = i & 511, row = rem >> 3, cc = rem & 7;
                uint32_t off = (uint32_t)(arr * 8192 + row * 128 +
                                          ((cc ^ (row & 7)) << 4));
                const __half* sp = (arr ? g_wlo : g_whi) +
                    (size_t)(512 + o0 + row) * C_DIM + kc0 + cc * 8;
                cp_async16(sWa + off, (const void*)sp);
            }
            for (int i = tid; i < 512; i += 128) {
                int row = i >> 3, cc = i & 7;
                uint32_t off = (uint32_t)(row * 128 + ((cc ^ (row & 7)) << 4));
                cp_async16(sXa + off,
                           (const void*)(xb + (size_t)(n0 + row) * C_DIM + kc0 + cc * 8));
            }
            CP_COMMIT();
            CP_WAIT0();
            __syncthreads();

#pragma unroll
            for (int ks = 0; ks < 4; ks++) {
                uint32_t ahi[4], alo[4];
                {
                    uint32_t off = (uint32_t)(aRow * 128 +
                        (((ks * 2 + aCs) ^ (aRow & 7)) << 4));
                    ldsm_x4(sWa + off, ahi);
                    ldsm_x4(sWa + 8192 + off, alo);
                }
#pragma unroll
                for (int g = 0; g < 4; g++) {
                    uint32_t bhi[4];
                    int row = g * 16 + trow;
                    ldsm_x4(sXa + (uint32_t)(row * 128 +
                            (((ks * 2 + csel) ^ (row & 7)) << 4)), bhi);
#pragma unroll
                    for (int hf = 0; hf < 2; hf++) {
                        float* d = acc[g * 2 + hf];
                        const int o = hf * 2;
                        mma16816(d, ahi, bhi[o], bhi[o + 1]);
                        mma16816(d, alo, bhi[o], bhi[o + 1]);
                    }
                }
            }
            __syncthreads();
        }

        const int r  = lane >> 2;
        const int c0 = 2 * (lane & 3);
        const int ol0 = o0 + m0 + r;
        const float bi0 = bias[512 + ol0];
        const float bi1 = bias[512 + ol0 + 8];
#pragma unroll
        for (int nt = 0; nt < 8; nt++) {
            int n = n0 + nt * 8 + c0;
            __half2 h0 = __floats2half2_rn(acc[nt][0] + bi0, acc[nt][1] + bi0);
            __half2 h1 = __floats2half2_rn(acc[nt][2] + bi1, acc[nt][3] + bi1);
            int bh0 = b * 8 + (ol0 >> 5);
            int ch0 = ol0 & 31;
            int ol1 = ol0 + 8;
            int bh1 = b * 8 + (ol1 >> 5);
            int ch1 = ol1 & 31;
            *(__half2*)(g_Vhi + ((size_t)bh0 * HDIM + ch0) * N_TOK + n) = h0;
            *(__half2*)(g_Vhi + ((size_t)bh1 * HDIM + ch1) * N_TOK + n) = h1;
        }
    }
}

// ===========================================================================
// Kernel E: flash attention, 128-query CTA, warp w owns rows [32w, 32w+32)
// (2 strips of 16), all 4 jp tokens per warp. Single wave (512 CTAs, occ 5).
// Q pre-scaled by KL2 -> phi = ex2(cvt(sacc)). One __syncthreads per iter.
// grid (32 q-tiles, 16 bh), block 128, KT=64, cp.async 2-stage.
// smem: 8K (Q) + 8K (K x2) + 8K (V x2) = 24 KB
// ===========================================================================
#define NIT (N_TOK / 64)

__global__ __launch_bounds__(128, 5) void attn_kernel(float* __restrict__ out)
{
    __shared__ __align__(16) uint8_t sQ[128 * 64];
    __shared__ __align__(16) uint8_t sK[2][64 * 64];
    __shared__ __align__(16) uint8_t sV[2][32 * 128];

    const int tid  = threadIdx.x;
    const int lane = tid & 31;
    const int warp = tid >> 5;
    const int q0   = blockIdx.x * 128;
    const int bh   = blockIdx.y;
    const int b    = bh >> 3, h = bh & 7;

    const uint32_t sQa = smem_to_u32(sQ);
    const uint32_t sKa = smem_to_u32(sK);
    const uint32_t sVa = smem_to_u32(sV);

    const uint4* kh4 = (const uint4*)(g_Khi + (size_t)bh * N_TOK * HDIM);
    const uint4* vh4 = (const uint4*)(g_Vhi + (size_t)bh * HDIM * N_TOK);

    uint32_t kOff[2], kGi[2], vOff[2], vGi[2];
#pragma unroll
    for (int i = 0; i < 2; i++) {
        int idx = tid + 128 * i;
        int row = idx >> 2, c = idx & 3;
        kOff[i] = (uint32_t)(row * 64 + ((c ^ ((row >> 1) & 3)) << 4));
        kGi[i]  = (uint32_t)(row * 4 + c);
        int ch = idx >> 3, cv = idx & 7;
        vOff[i] = (uint32_t)(ch * 128 + ((cv ^ (ch & 7)) << 4));
        vGi[i]  = (uint32_t)(ch * 512 + cv);
    }

    // ---- load Q tile (128 rows x 4 chunks) ----
    {
        const uint4* qh4 = (const uint4*)(g_Qhi + ((size_t)bh * N_TOK + q0) * HDIM);
        for (int idx = tid; idx < 512; idx += 128) {
            int row = idx >> 2, c = idx & 3;
            uint4 v = qh4[idx];
            uint32_t off = (uint32_t)(row * 64 + ((c ^ ((row >> 1) & 3)) << 4));
            STS128(v.x, v.y, v.z, v.w, sQa + off);
        }
    }

    // ---- prefetch stage 0 ----
#pragma unroll
    for (int i = 0; i < 2; i++) {
        cp_async16(sKa + kOff[i], (const void*)(kh4 + kGi[i]));
        cp_async16(sVa + vOff[i], (const void*)(vh4 + vGi[i]));
    }
    CP_COMMIT();
    __syncthreads();   // Q tile visible

    // ---- Q A-fragments: 2 strips, rows warp*32 + st*16 + (lane&15) ----
    uint32_t qh[2][2][4];
#pragma unroll
    for (int st = 0; st < 2; st++) {
        int row = warp * 32 + st * 16 + (lane & 15);
        int sw  = (row >> 1) & 3;
#pragma unroll
        for (int kk = 0; kk < 2; kk++) {
            int ch = kk * 2 + (lane >> 4);
            ldsm_x4(sQa + (uint32_t)(row * 64 + ((ch ^ sw) << 4)), qh[st][kk]);
        }
    }

    float oacc[2][4][4];
#pragma unroll
    for (int st = 0; st < 2; st++)
#pragma unroll
        for (int n = 0; n < 4; n++)
#pragma unroll
            for (int r = 0; r < 4; r++) oacc[st][n][r] = 0.f;
    float rs[2][2] = {{0.f, 0.f}, {0.f, 0.f}};

    const int trow = (lane & 7) + ((lane >> 4) << 3);
    const int csel = (lane >> 3) & 1;
    const int ksw  = (trow >> 1) & 3;
    uint32_t kfa[2];
#pragma unroll
    for (int kk = 0; kk < 2; kk++) {
        int ch = kk * 2 + csel;
        kfa[kk] = (uint32_t)(trow * 64 + ((ch ^ ksw) << 4));
    }
    const int vxr = trow & 7;

    for (int it = 0; it < NIT; ++it) {
        const int s = it & 1;

        CP_WAIT0();
        __syncthreads();   // stage s ready AND stage s^1 reads retired

        if (it + 1 < NIT) {
            const uint32_t kg = (uint32_t)(it + 1) * 256;
            const uint32_t vg = (uint32_t)(it + 1) * 8;
            const uint32_t sb = (uint32_t)((s ^ 1) * 4096);
#pragma unroll
            for (int i = 0; i < 2; i++) {
                cp_async16(sKa + sb + kOff[i], (const void*)(kh4 + kg + kGi[i]));
                cp_async16(sVa + sb + vOff[i], (const void*)(vh4 + vg + vGi[i]));
            }
            CP_COMMIT();
        }

        const uint32_t kS = sKa + (uint32_t)(s * 4096);
        const uint32_t vS = sVa + (uint32_t)(s * 4096);

#pragma unroll
        for (int jp = 0; jp < 4; jp++) {
            uint32_t khf[2][4];
#pragma unroll
            for (int kk = 0; kk < 2; kk++)
                ldsm_x4(kS + (uint32_t)(jp * 1024) + kfa[kk], khf[kk]);

            uint32_t vhf[8];
            {
                int cXor = (2 * jp + csel) ^ vxr;
#pragma unroll
                for (int g = 0; g < 2; g++) {
                    int ch = g * 16 + trow;
                    ldsm_x4(vS + (uint32_t)(ch * 128 + (cXor << 4)),
                            &vhf[g * 4]);
                }
            }

#pragma unroll
            for (int st = 0; st < 2; st++) {
                float sacc[2][4];
#pragma unroll
                for (int hf = 0; hf < 2; hf++)
#pragma unroll
                    for (int r = 0; r < 4; r++) sacc[hf][r] = 0.f;
#pragma unroll
                for (int hf = 0; hf < 2; hf++) {
                    const int o = hf * 2;
#pragma unroll
                    for (int kk = 0; kk < 2; kk++)
                        mma16816(sacc[hf], qh[st][kk],
                                 khf[kk][o], khf[kk][o + 1]);
                }

                // Q pre-scaled: phi = ex2(cvt_half2(sacc)) directly
                uint32_t phi[4];
                {
                    __half2 p0 = __floats2half2_rn(sacc[0][0], sacc[0][1]);
                    __half2 p1 = __floats2half2_rn(sacc[0][2], sacc[0][3]);
                    __half2 p2 = __floats2half2_rn(sacc[1][0], sacc[1][1]);
                    __half2 p3 = __floats2half2_rn(sacc[1][2], sacc[1][3]);
                    phi[0] = ex2_f16x2(*(uint32_t*)&p0);
                    phi[1] = ex2_f16x2(*(uint32_t*)&p1);
                    phi[2] = ex2_f16x2(*(uint32_t*)&p2);
                    phi[3] = ex2_f16x2(*(uint32_t*)&p3);
                }
                {
                    __half2 sr  = __hadd2(*(__half2*)&phi[0], *(__half2*)&phi[2]);
                    __half2 sr8 = __hadd2(*(__half2*)&phi[1], *(__half2*)&phi[3]);
                    float2 f  = __half22float2(sr);
                    float2 f8 = __half22float2(sr8);
                    rs[st][0] += f.x + f.y;
                    rs[st][1] += f8.x + f8.y;
                }

#pragma unroll
                for (int nt = 0; nt < 4; nt++)
                    mma16816(oacc[st][nt], phi, vhf[2 * nt], vhf[2 * nt + 1]);
            }
        }
    }

    // ---- epilogue: each warp owns its rows, no cross-warp reduction ----
    const int r  = lane >> 2;
    const int c0 = 2 * (lane & 3);
#pragma unroll
    for (int st = 0; st < 2; st++) {
        float r0 = rs[st][0], r1 = rs[st][1];
        r0 += __shfl_xor_sync(0xFFFFFFFFu, r0, 1);
        r0 += __shfl_xor_sync(0xFFFFFFFFu, r0, 2);
        r1 += __shfl_xor_sync(0xFFFFFFFFu, r1, 1);
        r1 += __shfl_xor_sync(0xFFFFFFFFu, r1, 2);
        const float inv0 = 1.f / r0;
        const float inv1 = 1.f / r1;
        const int token0 = q0 + warp * 32 + st * 16 + r;
#pragma unroll
        for (int nt = 0; nt < 4; nt++) {
            int ch = h * HDIM + nt * 8 + c0;
            float* p0 = out + ((size_t)b * C_DIM + ch) * N_TOK + token0;
            float* p1 = out + ((size_t)b * C_DIM + ch + 1) * N_TOK + token0;
            p0[0] = oacc[st][nt][0] * inv0;
            p1[0] = oacc[st][nt][1] * inv0;
            p0[8] = oacc[st][nt][2] * inv1;
            p1[8] = oacc[st][nt][3] * inv1;
        }
    }
}

// ===========================================================================
extern "C" void kernel_launch(void* const* d_in, const int* in_sizes, int n_in,
                              void* d_out, int out_size)
{
    const float* x    = (const float*)d_in[0];
    const float* w    = (const float*)d_in[1];
    const float* bias = (const float*)d_in[2];

    convert_x_kernel<<<dim3(N_TOK / 32, C_DIM / 32, BATCH), dim3(32, 8)>>>(x);
    convert_w_kernel<<<(3 * C_DIM * C_DIM + 255) / 256, 256>>>(w);

    qkv_gemm_kernel<<<dim3(N_TOK / 64, 12, BATCH), 128>>>(bias);

    attn_kernel<<<dim3(N_TOK / 128, 16), 128>>>((float*)d_out);
}

// round 17
// speedup vs baseline: 1.0903x; 1.0903x over previous
#include <cuda_runtime.h>
#include <cuda_fp16.h>
#include <math.h>
#include <stdint.h>

#define N_TOK 4096
#define C_DIM 256
#define BATCH 2
#define HEADS 8
#define HDIM 32

// exp2 scale folded into Q at GEMM epilogue: (1/sqrt(32)) * log2(e)
#define KL2_SCALE (0.17677669529663687f * 1.4426950408889634f)

// ===========================================================================
// Helpers
// ===========================================================================
__device__ __forceinline__ uint32_t smem_to_u32(const void* smem_ptr) {
    uint32_t addr;
    asm("{ .reg .u64 tmp; cvta.to.shared.u64 tmp, %1; cvt.u32.u64 %0, tmp; }"
        : "=r"(addr) : "l"(smem_ptr));
    return addr;
}

#define STS128(r0, r1, r2, r3, smem_addr) \
    asm volatile("st.shared.v4.b32 [%0], {%1, %2, %3, %4};" \
        :: "r"(smem_addr), "r"(r0), "r"(r1), "r"(r2), "r"(r3) : "memory")

__device__ __forceinline__ void cp_async16(uint32_t smem, const void* gptr) {
    asm volatile("cp.async.cg.shared.global [%0], [%1], 16;"
        :: "r"(smem), "l"(gptr) : "memory");
}
#define CP_COMMIT() asm volatile("cp.async.commit_group;" ::: "memory")
#define CP_WAIT0()  asm volatile("cp.async.wait_group 0;" ::: "memory")

__device__ __forceinline__ void ldsm_x4(uint32_t addr, uint32_t* r) {
    asm volatile("ldmatrix.sync.aligned.m8n8.x4.shared.b16 {%0,%1,%2,%3}, [%4];"
        : "=r"(r[0]), "=r"(r[1]), "=r"(r[2]), "=r"(r[3]) : "r"(addr));
}

__device__ __forceinline__ void mma16816(float* d, const uint32_t* a,
                                         uint32_t b0, uint32_t b1) {
    asm volatile(
        "mma.sync.aligned.m16n8k16.row.col.f32.f16.f16.f32 "
        "{%0,%1,%2,%3}, {%4,%5,%6,%7}, {%8,%9}, {%0,%1,%2,%3};"
        : "+f"(d[0]), "+f"(d[1]), "+f"(d[2]), "+f"(d[3])
        : "r"(a[0]), "r"(a[1]), "r"(a[2]), "r"(a[3]), "r"(b0), "r"(b1));
}

__device__ __forceinline__ uint32_t ex2_f16x2(uint32_t x) {
    uint32_t y;
    asm("ex2.approx.f16x2 %0, %1;" : "=r"(y) : "r"(x));
    return y;
}

// ===========================================================================
// Global scratch (no allocations allowed)
// ===========================================================================
__device__ __half g_xT[(size_t)BATCH * N_TOK * C_DIM];     // [b][n][c] hi only
__device__ __half g_whi[(size_t)3 * C_DIM * C_DIM];        // [o][c]
__device__ __half g_wlo[(size_t)3 * C_DIM * C_DIM];
__device__ __half g_Qhi[(size_t)16 * N_TOK * HDIM];        // [bh][tok][ch], pre-scaled by KL2
__device__ __half g_Khi[(size_t)16 * N_TOK * HDIM];        // [bh][tok][ch]
__device__ __half g_Vhi[(size_t)16 * HDIM * N_TOK];        // [bh][ch][tok]

// ===========================================================================
// Kernel A: transpose x: [b][c][n] fp32 -> [b][n][c] fp16 (hi only)
// ===========================================================================
__global__ __launch_bounds__(256) void convert_x_kernel(const float* __restrict__ x)
{
    __shared__ float t[32][33];
    const int n0 = blockIdx.x * 32;
    const int c0 = blockIdx.y * 32;
    const int b  = blockIdx.z;

    const float* src = x + ((size_t)b * C_DIM + c0) * N_TOK;
    for (int cy = threadIdx.y; cy < 32; cy += 8)
        t[cy][threadIdx.x] = src[(size_t)cy * N_TOK + n0 + threadIdx.x];
    __syncthreads();

    __half* hi = g_xT + ((size_t)b * N_TOK + n0) * C_DIM + c0;
    for (int ny = threadIdx.y; ny < 32; ny += 8)
        hi[(size_t)ny * C_DIM + threadIdx.x] =
            __float2half_rn(t[threadIdx.x][ny]);
}

// ===========================================================================
// Kernel B: split w: [o][c] fp32 -> hi/lo fp16 (same layout)
// ===========================================================================
__global__ __launch_bounds__(256) void convert_w_kernel(const float* __restrict__ w)
{
    int idx = blockIdx.x * 256 + threadIdx.x;
    if (idx < 3 * C_DIM * C_DIM) {
        float v = w[idx];
        __half h1 = __float2half_rn(v);
        g_whi[idx] = h1;
        g_wlo[idx] = __float2half_rn(v - __half2float(h1));
    }
}

// ===========================================================================
// Merged QKV GEMM kernel. grid (64, 12, 2), block 128.
//   blockIdx.y 0..7  : QK branch — out[n][o], A = xT rows, B = w hi/lo rows
//                      Q outputs (o<256) are pre-scaled by KL2_SCALE.
//   blockIdx.y 8..11 : V branch  — out[o][n], A = w hi/lo rows, B = xT rows
// ===========================================================================
__global__ __launch_bounds__(128) void qkv_gemm_kernel(const float* __restrict__ bias)
{
    __shared__ __align__(16) uint8_t smem[3 * 8192];

    const int tid  = threadIdx.x;
    const int lane = tid & 31;
    const int warp = tid >> 5;
    const int n0   = blockIdx.x * 64;
    const int b    = blockIdx.z;
    const int m0   = warp * 16;

    const int trow = (lane & 7) + ((lane >> 4) << 3);
    const int csel = (lane >> 3) & 1;
    const int aRow = m0 + (lane & 15);
    const int aCs  = lane >> 4;

    float acc[8][4];
#pragma unroll
    for (int i = 0; i < 8; i++)
#pragma unroll
        for (int j = 0; j < 4; j++) acc[i][j] = 0.f;

    const __half* xb = g_xT + (size_t)b * N_TOK * C_DIM;

    if (blockIdx.y < 8) {
        // ---------------- QK branch ----------------
        const int o0 = blockIdx.y * 64;   // 0..448
        const uint32_t sXa = smem_to_u32(smem);           // 8 KB x tile
        const uint32_t sWa = smem_to_u32(smem + 8192);    // 16 KB w hi/lo

        for (int kc = 0; kc < 4; kc++) {
            const int kc0 = kc * 64;
            for (int i = tid; i < 512; i += 128) {
                int row = i >> 3, cc = i & 7;
                uint32_t off = (uint32_t)(row * 128 + ((cc ^ (row & 7)) << 4));
                cp_async16(sXa + off,
                           (const void*)(xb + (size_t)(n0 + row) * C_DIM + kc0 + cc * 8));
            }
            for (int i = tid; i < 1024; i += 128) {
                int arr = i >> 9, rem = i & 511, row = rem >> 3, cc = rem & 7;
                uint32_t off = (uint32_t)(arr * 8192 + row * 128 +
                                          ((cc ^ (row & 7)) << 4));
                const __half* sp = (arr ? g_wlo : g_whi) +
                    (size_t)(o0 + row) * C_DIM + kc0 + cc * 8;
                cp_async16(sWa + off, (const void*)sp);
            }
            CP_COMMIT();
            CP_WAIT0();
            __syncthreads();

#pragma unroll
            for (int ks = 0; ks < 4; ks++) {
                uint32_t ahi[4];
                ldsm_x4(sXa + (uint32_t)(aRow * 128 +
                        (((ks * 2 + aCs) ^ (aRow & 7)) << 4)), ahi);
#pragma unroll
                for (int g = 0; g < 4; g++) {
                    uint32_t bhi[4], blo[4];
                    int row = g * 16 + trow;
                    uint32_t off = (uint32_t)(row * 128 +
                        (((ks * 2 + csel) ^ (row & 7)) << 4));
                    ldsm_x4(sWa + off, bhi);
                    ldsm_x4(sWa + 8192 + off, blo);
#pragma unroll
                    for (int hf = 0; hf < 2; hf++) {
                        float* d = acc[g * 2 + hf];
                        const int o = hf * 2;
                        mma16816(d, ahi, bhi[o], bhi[o + 1]);
                        mma16816(d, ahi, blo[o], blo[o + 1]);
                    }
                }
            }
            __syncthreads();
        }

        const int r  = lane >> 2;
        const int c0 = 2 * (lane & 3);
        const int n  = n0 + m0 + r;
        const bool isK = (o0 >= 256);
        __half* dst = isK ? g_Khi : g_Qhi;
        const float sc = isK ? 1.f : KL2_SCALE;   // fold exp2 scale into Q
#pragma unroll
        for (int nt = 0; nt < 8; nt++) {
            int og = o0 + nt * 8 + c0;
            int ol = og & 255;
            int bh = b * 8 + (ol >> 5);
            int ch = ol & 31;
            float b0 = bias[og], b1 = bias[og + 1];
            __half2 h0 = __floats2half2_rn((acc[nt][0] + b0) * sc,
                                           (acc[nt][1] + b1) * sc);
            __half2 h1 = __floats2half2_rn((acc[nt][2] + b0) * sc,
                                           (acc[nt][3] + b1) * sc);
            size_t base = ((size_t)bh * N_TOK + n) * HDIM + ch;
            *(__half2*)(dst + base) = h0;
            *(__half2*)(dst + base + 8 * HDIM) = h1;
        }
    } else {
        // ---------------- V branch ----------------
        const int o0 = (blockIdx.y - 8) * 64;   // 0..192 (V-local)
        const uint32_t sWa = smem_to_u32(smem);           // 16 KB w hi/lo
        const uint32_t sXa = smem_to_u32(smem + 16384);   // 8 KB x tile

        for (int kc = 0; kc < 4; kc++) {
            const int kc0 = kc * 64;
            for (int i = tid; i < 1024; i += 128) {
                int arr = i >> 9, rem = i & 511, row = rem >> 3, cc = rem & 7;
                uint32_t off = (uint32_t)(arr * 8192 + row * 128 +
                                          ((cc ^ (row & 7)) << 4));
                const __half* sp = (arr ? g_wlo : g_whi) +
                    (size_t)(512 + o0 + row) * C_DIM + kc0 + cc * 8;
                cp_async16(sWa + off, (const void*)sp);
            }
            for (int i = tid; i < 512; i += 128) {
                int row = i >> 3, cc = i & 7;
                uint32_t off = (uint32_t)(row * 128 + ((cc ^ (row & 7)) << 4));
                cp_async16(sXa + off,
                           (const void*)(xb + (size_t)(n0 + row) * C_DIM + kc0 + cc * 8));
            }
            CP_COMMIT();
            CP_WAIT0();
            __syncthreads();

#pragma unroll
            for (int ks = 0; ks < 4; ks++) {
                uint32_t ahi[4], alo[4];
                {
                    uint32_t off = (uint32_t)(aRow * 128 +
                        (((ks * 2 + aCs) ^ (aRow & 7)) << 4));
                    ldsm_x4(sWa + off, ahi);
                    ldsm_x4(sWa + 8192 + off, alo);
                }
#pragma unroll
                for (int g = 0; g < 4; g++) {
                    uint32_t bhi[4];
                    int row = g * 16 + trow;
                    ldsm_x4(sXa + (uint32_t)(row * 128 +
                            (((ks * 2 + csel) ^ (row & 7)) << 4)), bhi);
#pragma unroll
                    for (int hf = 0; hf < 2; hf++) {
                        float* d = acc[g * 2 + hf];
                        const int o = hf * 2;
                        mma16816(d, ahi, bhi[o], bhi[o + 1]);
                        mma16816(d, alo, bhi[o], bhi[o + 1]);
                    }
                }
            }
            __syncthreads();
        }

        const int r  = lane >> 2;
        const int c0 = 2 * (lane & 3);
        const int ol0 = o0 + m0 + r;
        const float bi0 = bias[512 + ol0];
        const float bi1 = bias[512 + ol0 + 8];
#pragma unroll
        for (int nt = 0; nt < 8; nt++) {
            int n = n0 + nt * 8 + c0;
            __half2 h0 = __floats2half2_rn(acc[nt][0] + bi0, acc[nt][1] + bi0);
            __half2 h1 = __floats2half2_rn(acc[nt][2] + bi1, acc[nt][3] + bi1);
            int bh0 = b * 8 + (ol0 >> 5);
            int ch0 = ol0 & 31;
            int ol1 = ol0 + 8;
            int bh1 = b * 8 + (ol1 >> 5);
            int ch1 = ol1 & 31;
            *(__half2*)(g_Vhi + ((size_t)bh0 * HDIM + ch0) * N_TOK + n) = h0;
            *(__half2*)(g_Vhi + ((size_t)bh1 * HDIM + ch1) * N_TOK + n) = h1;
        }
    }
}

// ===========================================================================
// Kernel E: flash attention — round-14 shape (64-q tile, 16 rows/warp,
// occ 7, 1024 CTAs) + Q pre-scaled (no HMUL2) + single sync per iter.
// grid (64 q-tiles, 16 bh), block 128, KT=64, cp.async 2-stage.
// smem: 4K (Q) + 8K (K x2) + 8K (V x2) = 20 KB
// ===========================================================================
#define NIT (N_TOK / 64)

__global__ __launch_bounds__(128, 7) void attn_kernel(float* __restrict__ out)
{
    __shared__ __align__(16) uint8_t sQ[64 * 64];
    __shared__ __align__(16) uint8_t sK[2][64 * 64];
    __shared__ __align__(16) uint8_t sV[2][32 * 128];

    const int tid  = threadIdx.x;
    const int lane = tid & 31;
    const int warp = tid >> 5;
    const int q0   = blockIdx.x * 64;
    const int bh   = blockIdx.y;
    const int b    = bh >> 3, h = bh & 7;
    const int m0   = warp * 16;

    const uint32_t sQa = smem_to_u32(sQ);
    const uint32_t sKa = smem_to_u32(sK);
    const uint32_t sVa = smem_to_u32(sV);

    const uint4* kh4 = (const uint4*)(g_Khi + (size_t)bh * N_TOK * HDIM);
    const uint4* vh4 = (const uint4*)(g_Vhi + (size_t)bh * HDIM * N_TOK);

    uint32_t kOff[2], kGi[2], vOff[2], vGi[2];
#pragma unroll
    for (int i = 0; i < 2; i++) {
        int idx = tid + 128 * i;
        int row = idx >> 2, c = idx & 3;
        kOff[i] = (uint32_t)(row * 64 + ((c ^ ((row >> 1) & 3)) << 4));
        kGi[i]  = (uint32_t)(row * 4 + c);
        int ch = idx >> 3, cv = idx & 7;
        vOff[i] = (uint32_t)(ch * 128 + ((cv ^ (ch & 7)) << 4));
        vGi[i]  = (uint32_t)(ch * 512 + cv);
    }

    // ---- load Q tile ----
    {
        const uint4* qh4 = (const uint4*)(g_Qhi + ((size_t)bh * N_TOK + q0) * HDIM);
        for (int idx = tid; idx < 256; idx += 128) {
            int row = idx >> 2, c = idx & 3;
            uint4 v = qh4[idx];
            uint32_t off = (uint32_t)(row * 64 + ((c ^ ((row >> 1) & 3)) << 4));
            STS128(v.x, v.y, v.z, v.w, sQa + off);
        }
    }

    // ---- prefetch stage 0 ----
#pragma unroll
    for (int i = 0; i < 2; i++) {
        cp_async16(sKa + kOff[i], (const void*)(kh4 + kGi[i]));
        cp_async16(sVa + vOff[i], (const void*)(vh4 + vGi[i]));
    }
    CP_COMMIT();
    __syncthreads();   // Q tile visible

    // ---- Q A-fragments ----
    uint32_t qh[2][4];
    {
        int row = m0 + (lane & 15);
        int sw  = (row >> 1) & 3;
#pragma unroll
        for (int kk = 0; kk < 2; kk++) {
            int ch = kk * 2 + (lane >> 4);
            ldsm_x4(sQa + (uint32_t)(row * 64 + ((ch ^ sw) << 4)), qh[kk]);
        }
    }

    float oacc[4][4];
#pragma unroll
    for (int n = 0; n < 4; n++)
#pragma unroll
        for (int r = 0; r < 4; r++) oacc[n][r] = 0.f;
    float rs0 = 0.f, rs1 = 0.f;

    const int trow = (lane & 7) + ((lane >> 4) << 3);
    const int csel = (lane >> 3) & 1;
    const int ksw  = (trow >> 1) & 3;
    uint32_t kfa[2];
#pragma unroll
    for (int kk = 0; kk < 2; kk++) {
        int ch = kk * 2 + csel;
        kfa[kk] = (uint32_t)(trow * 64 + ((ch ^ ksw) << 4));
    }
    const int vxr = trow & 7;

    for (int it = 0; it < NIT; ++it) {
        const int s = it & 1;

        CP_WAIT0();
        __syncthreads();   // stage s ready AND stage s^1 reads retired

        if (it + 1 < NIT) {
            const uint32_t kg = (uint32_t)(it + 1) * 256;
            const uint32_t vg = (uint32_t)(it + 1) * 8;
            const uint32_t sb = (uint32_t)((s ^ 1) * 4096);
#pragma unroll
            for (int i = 0; i < 2; i++) {
                cp_async16(sKa + sb + kOff[i], (const void*)(kh4 + kg + kGi[i]));
                cp_async16(sVa + sb + vOff[i], (const void*)(vh4 + vg + vGi[i]));
            }
            CP_COMMIT();
        }

        const uint32_t kS = sKa + (uint32_t)(s * 4096);
        const uint32_t vS = sVa + (uint32_t)(s * 4096);

#pragma unroll
        for (int jp = 0; jp < 4; jp++) {
            uint32_t khf[2][4];
#pragma unroll
            for (int kk = 0; kk < 2; kk++)
                ldsm_x4(kS + (uint32_t)(jp * 1024) + kfa[kk], khf[kk]);

            float sacc[2][4];
#pragma unroll
            for (int hf = 0; hf < 2; hf++)
#pragma unroll
                for (int r = 0; r < 4; r++) sacc[hf][r] = 0.f;
#pragma unroll
            for (int hf = 0; hf < 2; hf++) {
                const int o = hf * 2;
#pragma unroll
                for (int kk = 0; kk < 2; kk++)
                    mma16816(sacc[hf], qh[kk], khf[kk][o], khf[kk][o + 1]);
            }

            // Q pre-scaled: phi = ex2(cvt_half2(sacc)) directly
            uint32_t phi[4];
            {
                __half2 p0 = __floats2half2_rn(sacc[0][0], sacc[0][1]);
                __half2 p1 = __floats2half2_rn(sacc[0][2], sacc[0][3]);
                __half2 p2 = __floats2half2_rn(sacc[1][0], sacc[1][1]);
                __half2 p3 = __floats2half2_rn(sacc[1][2], sacc[1][3]);
                phi[0] = ex2_f16x2(*(uint32_t*)&p0);
                phi[1] = ex2_f16x2(*(uint32_t*)&p1);
                phi[2] = ex2_f16x2(*(uint32_t*)&p2);
                phi[3] = ex2_f16x2(*(uint32_t*)&p3);
            }
            {
                __half2 sr  = __hadd2(*(__half2*)&phi[0], *(__half2*)&phi[2]);
                __half2 sr8 = __hadd2(*(__half2*)&phi[1], *(__half2*)&phi[3]);
                float2 f  = __half22float2(sr);
                float2 f8 = __half22float2(sr8);
                rs0 += f.x + f.y;
                rs1 += f8.x + f8.y;
            }

            uint32_t vhf[8];
            {
                int cXor = (2 * jp + csel) ^ vxr;
#pragma unroll
                for (int g = 0; g < 2; g++) {
                    int ch = g * 16 + trow;
                    ldsm_x4(vS + (uint32_t)(ch * 128 + (cXor << 4)),
                            &vhf[g * 4]);
                }
            }

#pragma unroll
            for (int nt = 0; nt < 4; nt++)
                mma16816(oacc[nt], phi, vhf[2 * nt], vhf[2 * nt + 1]);
        }
    }

    rs0 += __shfl_xor_sync(0xFFFFFFFFu, rs0, 1);
    rs0 += __shfl_xor_sync(0xFFFFFFFFu, rs0, 2);
    rs1 += __shfl_xor_sync(0xFFFFFFFFu, rs1, 1);
    rs1 += __shfl_xor_sync(0xFFFFFFFFu, rs1, 2);
    const float inv0 = 1.f / rs0;
    const float inv1 = 1.f / rs1;

    const int r  = lane >> 2;
    const int c0 = 2 * (lane & 3);
    const int token0 = q0 + m0 + r;
#pragma unroll
    for (int nt = 0; nt < 4; nt++) {
        int ch = h * HDIM + nt * 8 + c0;
        float* p0 = out + ((size_t)b * C_DIM + ch) * N_TOK + token0;
        float* p1 = out + ((size_t)b * C_DIM + ch + 1) * N_TOK + token0;
        p0[0] = oacc[nt][0] * inv0;
        p1[0] = oacc[nt][1] * inv0;
        p0[8] = oacc[nt][2] * inv1;
        p1[8] = oacc[nt][3] * inv1;
    }
}

// ===========================================================================
extern "C" void kernel_launch(void* const* d_in, const int* in_sizes, int n_in,
                              void* d_out, int out_size)
{
    const float* x    = (const float*)d_in[0];
    const float* w    = (const float*)d_in[1];
    const float* bias = (const float*)d_in[2];

    convert_x_kernel<<<dim3(N_TOK / 32, C_DIM / 32, BATCH), dim3(32, 8)>>>(x);
    convert_w_kernel<<<(3 * C_DIM * C_DIM + 255) / 256, 256>>>(w);

    qkv_gemm_kernel<<<dim3(N_TOK / 64, 12, BATCH), 128>>>(bias);

    attn_kernel<<<dim3(N_TOK / 64, 16), 128>>>((float*)d_out);
}